// round 4
// baseline (speedup 1.0000x reference)
#include <cuda_runtime.h>
#include <cuda_bf16.h>
#include <cstdint>
#include <math.h>

#define SEQ  8192
#define DIM  1024
#define NOUT 4096

// ---------------- device scratch (no allocations allowed) ----------------
__device__ __nv_bfloat16 g_x_hi[SEQ * DIM];
__device__ __nv_bfloat16 g_x_lo[SEQ * DIM];
__device__ __nv_bfloat16 g_w_hi[NOUT * DIM];
__device__ __nv_bfloat16 g_w_lo[NOUT * DIM];

// ---------------- PTX helpers (base-target sm_80/sm_90 features only) ----------------
__device__ __forceinline__ uint32_t smem_u32(const void* p) {
    uint32_t a;
    asm("{ .reg .u64 t; cvta.to.shared.u64 t, %1; cvt.u32.u64 %0, t; }" : "=r"(a) : "l"(p));
    return a;
}
__device__ __forceinline__ void cp_async16(uint32_t smem, const void* gmem) {
    asm volatile("cp.async.cg.shared.global [%0], [%1], 16;" :: "r"(smem), "l"(gmem) : "memory");
}
__device__ __forceinline__ void cp_commit() {
    asm volatile("cp.async.commit_group;" ::: "memory");
}
template <int N>
__device__ __forceinline__ void cp_wait() {
    asm volatile("cp.async.wait_group %0;" :: "n"(N) : "memory");
}
__device__ __forceinline__ void ldsm_x4(uint32_t* r, uint32_t addr) {
    asm volatile("ldmatrix.sync.aligned.m8n8.x4.shared.b16 {%0,%1,%2,%3}, [%4];"
                 : "=r"(r[0]), "=r"(r[1]), "=r"(r[2]), "=r"(r[3]) : "r"(addr));
}
__device__ __forceinline__ void mma_bf16(float* c, const uint32_t* a, const uint32_t* b) {
    asm volatile(
        "mma.sync.aligned.m16n8k16.row.col.f32.bf16.bf16.f32 "
        "{%0,%1,%2,%3}, {%4,%5,%6,%7}, {%8,%9}, {%0,%1,%2,%3};"
        : "+f"(c[0]), "+f"(c[1]), "+f"(c[2]), "+f"(c[3])
        : "r"(a[0]), "r"(a[1]), "r"(a[2]), "r"(a[3]), "r"(b[0]), "r"(b[1]));
}

// ---------------- fp32 -> bf16 hi/lo split ----------------
__global__ void split_kernel(const float* __restrict__ src,
                             __nv_bfloat16* __restrict__ hi,
                             __nv_bfloat16* __restrict__ lo, int n4) {
    int i = blockIdx.x * blockDim.x + threadIdx.x;
    if (i >= n4) return;
    float4 v = reinterpret_cast<const float4*>(src)[i];
    float vv[4] = {v.x, v.y, v.z, v.w};
    unsigned short h[4], l[4];
#pragma unroll
    for (int j = 0; j < 4; j++) {
        __nv_bfloat16 hb = __float2bfloat16(vv[j]);
        __nv_bfloat16 lb = __float2bfloat16(vv[j] - __bfloat162float(hb));
        h[j] = __bfloat16_as_ushort(hb);
        l[j] = __bfloat16_as_ushort(lb);
    }
    reinterpret_cast<ushort4*>(hi)[i] = make_ushort4(h[0], h[1], h[2], h[3]);
    reinterpret_cast<ushort4*>(lo)[i] = make_ushort4(l[0], l[1], l[2], l[3]);
}

// ---------------- mma.sync GEMM + bias + tanh ----------------
// CTA tile 128x128, K-stage 64 bf16, 3 fused terms -> 48 stage-iterations.
// 8 warps in 2(M) x 4(N) grid; warp tile 64x32 via m16n8k16.
static constexpr int NSTAGES  = 4;
static constexpr int A_BYTES  = 128 * 128;      // 128 rows x 64 bf16 (128B/row)
static constexpr int STAGE_B  = 2 * A_BYTES;    // A + B = 32 KB
static constexpr int SMEM_GB  = NSTAGES * STAGE_B;  // 128 KB
static constexpr int ITERS    = 3 * (DIM / 64); // 48

__global__ __launch_bounds__(256, 1)
void gemm_kernel(const float* __restrict__ bias, float* __restrict__ out) {
    extern __shared__ char smem[];
    const uint32_t sb = smem_u32(smem);
    const int tid  = threadIdx.x;
    const int lane = tid & 31;
    const int wid  = tid >> 5;
    const int wm   = wid >> 2;       // 0..1 -> 64 rows
    const int wn   = wid & 3;        // 0..3 -> 32 cols
    const int m_base = blockIdx.y * 128;
    const int n_base = blockIdx.x * 128;

    // cp.async addressing: thread t -> row r = t>>1 (0..127), half h = t&1, 4x16B units
    const int r_ld = tid >> 1;
    const int h_ld = tid & 1;

    const __nv_bfloat16* xs[3] = {g_x_hi, g_x_hi, g_x_lo};
    const __nv_bfloat16* ws[3] = {g_w_hi, g_w_lo, g_w_hi};

    auto load_stage = [&](int it) {
        const int term = it >> 4;
        const int kc   = (it & 15) * 64;
        const int st   = (it % NSTAGES) * STAGE_B;
        const __nv_bfloat16* ga = xs[term] + (size_t)(m_base + r_ld) * DIM + kc;
        const __nv_bfloat16* gb = ws[term] + (size_t)(n_base + r_ld) * DIM + kc;
        const uint32_t sa = sb + st + r_ld * 128;
        const uint32_t sbb = sb + st + A_BYTES + r_ld * 128;
        const int swz = r_ld & 7;
#pragma unroll
        for (int j = 0; j < 4; j++) {
            const int u = h_ld * 4 + j;
            const uint32_t so = (uint32_t)((u ^ swz) << 4);
            cp_async16(sa + so, ga + u * 8);
            cp_async16(sbb + so, gb + u * 8);
        }
    };

    float acc[4][4][4];
#pragma unroll
    for (int i = 0; i < 4; i++)
#pragma unroll
        for (int j = 0; j < 4; j++)
#pragma unroll
            for (int k = 0; k < 4; k++) acc[i][j][k] = 0.0f;

    // prologue: stages 0..2 in flight
    load_stage(0); cp_commit();
    load_stage(1); cp_commit();
    load_stage(2); cp_commit();

    // per-lane ldmatrix row constants
    const int rA  = lane & 15;        // A: row within m16 tile
    const int uhA = lane >> 4;        // A: k 16B-unit half
    const int rB  = lane;             // B: row within warp's 32 n-rows (4 n-tiles)

    for (int it = 0; it < ITERS; it++) {
        if (it <= 45)      cp_wait<2>();
        else if (it == 46) cp_wait<1>();
        else               cp_wait<0>();
        __syncthreads();

        if (it + 3 < ITERS) { load_stage(it + 3); cp_commit(); }

        const uint32_t aBase = sb + (it % NSTAGES) * STAGE_B;
        const uint32_t bBase = aBase + A_BYTES;
#pragma unroll
        for (int ks = 0; ks < 4; ks++) {
            uint32_t a[4][4];
#pragma unroll
            for (int i = 0; i < 4; i++) {
                const int row = wm * 64 + i * 16 + rA;
                const uint32_t u = (uint32_t)((ks * 2 + uhA) ^ (row & 7));
                ldsm_x4(a[i], aBase + row * 128 + (u << 4));
            }
            // B: n-major [n][k] SMEM tile + row.col mma => NON-trans ldmatrix.
            // Lane group g (8 lanes) addresses n-rows of n-tile g at k-unit u;
            // result t[g] = b-fragment half 'uh' for n-tile g.
            uint32_t b[4][2];
#pragma unroll
            for (int uh = 0; uh < 2; uh++) {
                const int row = wn * 32 + rB;
                const uint32_t u = (uint32_t)((ks * 2 + uh) ^ (row & 7));
                uint32_t t[4];
                ldsm_x4(t, bBase + row * 128 + (u << 4));
                b[0][uh] = t[0]; b[1][uh] = t[1]; b[2][uh] = t[2]; b[3][uh] = t[3];
            }
#pragma unroll
            for (int i = 0; i < 4; i++)
#pragma unroll
                for (int j = 0; j < 4; j++) mma_bf16(acc[i][j], a[i], b[j]);
        }
        __syncthreads();
    }

    // epilogue: bias + tanh + float2 stores
#pragma unroll
    for (int j = 0; j < 4; j++) {
        const int col0 = n_base + wn * 32 + j * 8 + (lane & 3) * 2;
        const float2 bv = *reinterpret_cast<const float2*>(bias + col0);
#pragma unroll
        for (int i = 0; i < 4; i++) {
            const int row0 = m_base + wm * 64 + i * 16 + (lane >> 2);
            float2 v0, v1;
            v0.x = tanhf(acc[i][j][0] + bv.x);
            v0.y = tanhf(acc[i][j][1] + bv.y);
            v1.x = tanhf(acc[i][j][2] + bv.x);
            v1.y = tanhf(acc[i][j][3] + bv.y);
            *reinterpret_cast<float2*>(out + (size_t)row0 * NOUT + col0) = v0;
            *reinterpret_cast<float2*>(out + (size_t)(row0 + 8) * NOUT + col0) = v1;
        }
    }
}

// ---------------- host launch ----------------
extern "C" void kernel_launch(void* const* d_in, const int* in_sizes, int n_in,
                              void* d_out, int out_size) {
    const float *x = nullptr, *W = nullptr, *b = nullptr;
    for (int i = 0; i < n_in; i++) {
        if (in_sizes[i] == SEQ * DIM)       x = (const float*)d_in[i];
        else if (in_sizes[i] == NOUT * DIM) W = (const float*)d_in[i];
        else if (in_sizes[i] == NOUT)       b = (const float*)d_in[i];
    }
    float* out = (float*)d_out;

    void *xh, *xl, *wh, *wl;
    cudaGetSymbolAddress(&xh, g_x_hi);
    cudaGetSymbolAddress(&xl, g_x_lo);
    cudaGetSymbolAddress(&wh, g_w_hi);
    cudaGetSymbolAddress(&wl, g_w_lo);

    split_kernel<<<(SEQ * DIM / 4) / 256, 256>>>(x, (__nv_bfloat16*)xh, (__nv_bfloat16*)xl,
                                                 SEQ * DIM / 4);
    split_kernel<<<(NOUT * DIM / 4) / 256, 256>>>(W, (__nv_bfloat16*)wh, (__nv_bfloat16*)wl,
                                                  NOUT * DIM / 4);

    static bool attr_set = false;
    if (!attr_set) {
        cudaFuncSetAttribute(gemm_kernel, cudaFuncAttributeMaxDynamicSharedMemorySize, SMEM_GB);
        attr_set = true;
    }
    dim3 grid(NOUT / 128, SEQ / 128);  // (32, 64)
    gemm_kernel<<<grid, 256, SMEM_GB>>>(b, out);
}

// round 5
// speedup vs baseline: 1.5539x; 1.5539x over previous
#include <cuda_runtime.h>
#include <cuda_bf16.h>
#include <cstdint>
#include <math.h>

#define SEQ  8192
#define DIM  1024
#define NOUT 4096

// ---------------- device scratch (no allocations allowed) ----------------
__device__ __nv_bfloat16 g_x_hi[SEQ * DIM];
__device__ __nv_bfloat16 g_x_lo[SEQ * DIM];
__device__ __nv_bfloat16 g_w_hi[NOUT * DIM];
__device__ __nv_bfloat16 g_w_lo[NOUT * DIM];

// ---------------- PTX helpers (base-target sm_80/sm_90 features only) ----------------
__device__ __forceinline__ uint32_t smem_u32(const void* p) {
    uint32_t a;
    asm("{ .reg .u64 t; cvta.to.shared.u64 t, %1; cvt.u32.u64 %0, t; }" : "=r"(a) : "l"(p));
    return a;
}
__device__ __forceinline__ void cp_async16(uint32_t smem, const void* gmem) {
    asm volatile("cp.async.cg.shared.global [%0], [%1], 16;" :: "r"(smem), "l"(gmem) : "memory");
}
__device__ __forceinline__ void cp_commit() {
    asm volatile("cp.async.commit_group;" ::: "memory");
}
template <int N>
__device__ __forceinline__ void cp_wait() {
    asm volatile("cp.async.wait_group %0;" :: "n"(N) : "memory");
}
__device__ __forceinline__ void ldsm_x4(uint32_t* r, uint32_t addr) {
    asm volatile("ldmatrix.sync.aligned.m8n8.x4.shared.b16 {%0,%1,%2,%3}, [%4];"
                 : "=r"(r[0]), "=r"(r[1]), "=r"(r[2]), "=r"(r[3]) : "r"(addr));
}
__device__ __forceinline__ void mma_bf16(float* c, const uint32_t* a, const uint32_t* b) {
    asm volatile(
        "mma.sync.aligned.m16n8k16.row.col.f32.bf16.bf16.f32 "
        "{%0,%1,%2,%3}, {%4,%5,%6,%7}, {%8,%9}, {%0,%1,%2,%3};"
        : "+f"(c[0]), "+f"(c[1]), "+f"(c[2]), "+f"(c[3])
        : "r"(a[0]), "r"(a[1]), "r"(a[2]), "r"(a[3]), "r"(b[0]), "r"(b[1]));
}

// ---------------- fp32 -> bf16 hi/lo split (x and W in ONE kernel) ----------------
static constexpr int XBLOCKS = (SEQ * DIM / 4) / 256;   // 8192
static constexpr int WBLOCKS = (NOUT * DIM / 4) / 256;  // 4096

__global__ void split_all_kernel(const float* __restrict__ x, const float* __restrict__ W) {
    const int bid = blockIdx.x;
    const float* src;
    __nv_bfloat16 *hi, *lo;
    int i;
    if (bid < XBLOCKS) {
        src = x; hi = g_x_hi; lo = g_x_lo;
        i = bid * 256 + threadIdx.x;
    } else {
        src = W; hi = g_w_hi; lo = g_w_lo;
        i = (bid - XBLOCKS) * 256 + threadIdx.x;
    }
    float4 v = reinterpret_cast<const float4*>(src)[i];
    float vv[4] = {v.x, v.y, v.z, v.w};
    unsigned short h[4], l[4];
#pragma unroll
    for (int j = 0; j < 4; j++) {
        __nv_bfloat16 hb = __float2bfloat16(vv[j]);
        __nv_bfloat16 lb = __float2bfloat16(vv[j] - __bfloat162float(hb));
        h[j] = __bfloat16_as_ushort(hb);
        l[j] = __bfloat16_as_ushort(lb);
    }
    reinterpret_cast<ushort4*>(hi)[i] = make_ushort4(h[0], h[1], h[2], h[3]);
    reinterpret_cast<ushort4*>(lo)[i] = make_ushort4(l[0], l[1], l[2], l[3]);
}

// ---------------- mma.sync GEMM + bias + tanh ----------------
// CTA tile 128x128, K-stage 64 bf16, 3 fused terms -> 48 stage-iterations.
// 8 warps in 2(M) x 4(N) grid; warp tile 64x32 via m16n8k16.
// Register-double-buffered fragments; single barrier per stage; 5 cp.async stages.
static constexpr int NSTAGES  = 5;
static constexpr int A_BYTES  = 128 * 128;          // 128 rows x 64 bf16 (128B/row)
static constexpr int STAGE_B  = 2 * A_BYTES;        // A + B = 32 KB
static constexpr int SMEM_GB  = NSTAGES * STAGE_B;  // 160 KB
static constexpr int ITERS    = 3 * (DIM / 64);     // 48

__global__ __launch_bounds__(256, 1)
void gemm_kernel(const float* __restrict__ bias, float* __restrict__ out) {
    extern __shared__ char smem[];
    const uint32_t sb = smem_u32(smem);
    const int tid  = threadIdx.x;
    const int lane = tid & 31;
    const int wid  = tid >> 5;
    const int wm   = wid >> 2;       // 0..1 -> 64 rows
    const int wn   = wid & 3;        // 0..3 -> 32 cols
    const int m_base = blockIdx.y * 128;
    const int n_base = blockIdx.x * 128;

    // cp.async addressing: thread t -> row r = t>>1 (0..127), half h = t&1, 4x16B units
    const int r_ld = tid >> 1;
    const int h_ld = tid & 1;

    const __nv_bfloat16* xs[3] = {g_x_hi, g_x_hi, g_x_lo};
    const __nv_bfloat16* ws[3] = {g_w_hi, g_w_lo, g_w_hi};

    auto load_stage = [&](int it) {
        const int term = it >> 4;
        const int kc   = (it & 15) * 64;
        const int st   = (it % NSTAGES) * STAGE_B;
        const __nv_bfloat16* ga = xs[term] + (size_t)(m_base + r_ld) * DIM + kc;
        const __nv_bfloat16* gb = ws[term] + (size_t)(n_base + r_ld) * DIM + kc;
        const uint32_t sa  = sb + st + r_ld * 128;
        const uint32_t sbb = sb + st + A_BYTES + r_ld * 128;
        const int swz = r_ld & 7;
#pragma unroll
        for (int j = 0; j < 4; j++) {
            const int u = h_ld * 4 + j;
            const uint32_t so = (uint32_t)((u ^ swz) << 4);
            cp_async16(sa + so, ga + u * 8);
            cp_async16(sbb + so, gb + u * 8);
        }
    };

    float acc[4][4][4];
#pragma unroll
    for (int i = 0; i < 4; i++)
#pragma unroll
        for (int j = 0; j < 4; j++)
#pragma unroll
            for (int k = 0; k < 4; k++) acc[i][j][k] = 0.0f;

    // prologue: stages 0..3 in flight
    load_stage(0); cp_commit();
    load_stage(1); cp_commit();
    load_stage(2); cp_commit();
    load_stage(3); cp_commit();

    // per-lane ldmatrix row constants
    const int rA  = lane & 15;        // A: row within m16 tile
    const int uhA = lane >> 4;        // A: k 16B-unit half
    const int rB  = lane;             // B: row within warp's 32 n-rows (4 n-tiles)
    const int rowAc[4] = {wm * 64 + 0 * 16 + rA, wm * 64 + 1 * 16 + rA,
                          wm * 64 + 2 * 16 + rA, wm * 64 + 3 * 16 + rA};
    const int rowBc = wn * 32 + rB;

    // double-buffered fragments
    uint32_t a_f[2][4][4];
    uint32_t b_f[2][4][2];

    for (int it = 0; it < ITERS; it++) {
        if (it <= ITERS - 4)      cp_wait<3>();
        else if (it == ITERS - 3) cp_wait<2>();
        else if (it == ITERS - 2) cp_wait<1>();
        else                      cp_wait<0>();
        __syncthreads();
        // Top barrier proves every warp finished reading stage (it+4)%5 in iter
        // it-1, so issuing its overwrite now is safe; no trailing barrier needed.
        if (it + 4 < ITERS) { load_stage(it + 4); cp_commit(); }

        const uint32_t aBase = sb + (it % NSTAGES) * STAGE_B;
        const uint32_t bBase = aBase + A_BYTES;

        // preload ks=0 fragments into buffer 0
#pragma unroll
        for (int i = 0; i < 4; i++) {
            const uint32_t u = (uint32_t)(uhA ^ (rowAc[i] & 7));
            ldsm_x4(a_f[0][i], aBase + rowAc[i] * 128 + (u << 4));
        }
#pragma unroll
        for (int uh = 0; uh < 2; uh++) {
            const uint32_t u = (uint32_t)(uh ^ (rowBc & 7));
            uint32_t t[4];
            ldsm_x4(t, bBase + rowBc * 128 + (u << 4));
            b_f[0][0][uh] = t[0]; b_f[0][1][uh] = t[1];
            b_f[0][2][uh] = t[2]; b_f[0][3][uh] = t[3];
        }

#pragma unroll
        for (int ks = 0; ks < 4; ks++) {
            const int cur = ks & 1, nxt = cur ^ 1;
            if (ks < 3) {
                // prefetch ks+1 fragments while HMMAs of ks issue
#pragma unroll
                for (int i = 0; i < 4; i++) {
                    const uint32_t u = (uint32_t)(((ks + 1) * 2 + uhA) ^ (rowAc[i] & 7));
                    ldsm_x4(a_f[nxt][i], aBase + rowAc[i] * 128 + (u << 4));
                }
#pragma unroll
                for (int uh = 0; uh < 2; uh++) {
                    const uint32_t u = (uint32_t)(((ks + 1) * 2 + uh) ^ (rowBc & 7));
                    uint32_t t[4];
                    ldsm_x4(t, bBase + rowBc * 128 + (u << 4));
                    b_f[nxt][0][uh] = t[0]; b_f[nxt][1][uh] = t[1];
                    b_f[nxt][2][uh] = t[2]; b_f[nxt][3][uh] = t[3];
                }
            }
#pragma unroll
            for (int i = 0; i < 4; i++)
#pragma unroll
                for (int j = 0; j < 4; j++) mma_bf16(acc[i][j], a_f[cur][i], b_f[cur][j]);
        }
    }

    // epilogue: bias + tanh + float2 stores
#pragma unroll
    for (int j = 0; j < 4; j++) {
        const int col0 = n_base + wn * 32 + j * 8 + (lane & 3) * 2;
        const float2 bv = *reinterpret_cast<const float2*>(bias + col0);
#pragma unroll
        for (int i = 0; i < 4; i++) {
            const int row0 = m_base + wm * 64 + i * 16 + (lane >> 2);
            float2 v0, v1;
            v0.x = tanhf(acc[i][j][0] + bv.x);
            v0.y = tanhf(acc[i][j][1] + bv.y);
            v1.x = tanhf(acc[i][j][2] + bv.x);
            v1.y = tanhf(acc[i][j][3] + bv.y);
            *reinterpret_cast<float2*>(out + (size_t)row0 * NOUT + col0) = v0;
            *reinterpret_cast<float2*>(out + (size_t)(row0 + 8) * NOUT + col0) = v1;
        }
    }
}

// ---------------- host launch ----------------
extern "C" void kernel_launch(void* const* d_in, const int* in_sizes, int n_in,
                              void* d_out, int out_size) {
    const float *x = nullptr, *W = nullptr, *b = nullptr;
    for (int i = 0; i < n_in; i++) {
        if (in_sizes[i] == SEQ * DIM)       x = (const float*)d_in[i];
        else if (in_sizes[i] == NOUT * DIM) W = (const float*)d_in[i];
        else if (in_sizes[i] == NOUT)       b = (const float*)d_in[i];
    }
    float* out = (float*)d_out;

    split_all_kernel<<<XBLOCKS + WBLOCKS, 256>>>(x, W);

    static bool attr_set = false;
    if (!attr_set) {
        cudaFuncSetAttribute(gemm_kernel, cudaFuncAttributeMaxDynamicSharedMemorySize, SMEM_GB);
        attr_set = true;
    }
    dim3 grid(NOUT / 128, SEQ / 128);  // (32, 64)
    gemm_kernel<<<grid, 256, SMEM_GB>>>(b, out);
}

// round 6
// speedup vs baseline: 1.8495x; 1.1902x over previous
#include <cuda_runtime.h>
#include <cuda_bf16.h>
#include <cstdint>
#include <math.h>

#define SEQ  8192
#define DIM  1024
#define NOUT 4096

// ---------------- device scratch (no allocations allowed) ----------------
__device__ __nv_bfloat16 g_x_hi[SEQ * DIM];
__device__ __nv_bfloat16 g_x_lo[SEQ * DIM];
__device__ __nv_bfloat16 g_w_hi[NOUT * DIM];
__device__ __nv_bfloat16 g_w_lo[NOUT * DIM];

// ---------------- PTX helpers (base-target sm_80/sm_90 features only) ----------------
__device__ __forceinline__ uint32_t smem_u32(const void* p) {
    uint32_t a;
    asm("{ .reg .u64 t; cvta.to.shared.u64 t, %1; cvt.u32.u64 %0, t; }" : "=r"(a) : "l"(p));
    return a;
}
__device__ __forceinline__ void cp_async16(uint32_t smem, const void* gmem) {
    asm volatile("cp.async.cg.shared.global [%0], [%1], 16;" :: "r"(smem), "l"(gmem) : "memory");
}
__device__ __forceinline__ void cp_commit() {
    asm volatile("cp.async.commit_group;" ::: "memory");
}
template <int N>
__device__ __forceinline__ void cp_wait() {
    asm volatile("cp.async.wait_group %0;" :: "n"(N) : "memory");
}
__device__ __forceinline__ void ldsm_x4(uint32_t* r, uint32_t addr) {
    asm volatile("ldmatrix.sync.aligned.m8n8.x4.shared.b16 {%0,%1,%2,%3}, [%4];"
                 : "=r"(r[0]), "=r"(r[1]), "=r"(r[2]), "=r"(r[3]) : "r"(addr));
}
__device__ __forceinline__ void mma_bf16(float* c, const uint32_t* a, const uint32_t* b) {
    asm volatile(
        "mma.sync.aligned.m16n8k16.row.col.f32.bf16.bf16.f32 "
        "{%0,%1,%2,%3}, {%4,%5,%6,%7}, {%8,%9}, {%0,%1,%2,%3};"
        : "+f"(c[0]), "+f"(c[1]), "+f"(c[2]), "+f"(c[3])
        : "r"(a[0]), "r"(a[1]), "r"(a[2]), "r"(a[3]), "r"(b[0]), "r"(b[1]));
}

// ---------------- fp32 -> bf16 hi/lo split (x and W in ONE kernel) ----------------
static constexpr int XBLOCKS = (SEQ * DIM / 4) / 256;   // 8192
static constexpr int WBLOCKS = (NOUT * DIM / 4) / 256;  // 4096

__global__ void split_all_kernel(const float* __restrict__ x, const float* __restrict__ W) {
    const int bid = blockIdx.x;
    const float* src;
    __nv_bfloat16 *hi, *lo;
    int i;
    if (bid < XBLOCKS) {
        src = x; hi = g_x_hi; lo = g_x_lo;
        i = bid * 256 + threadIdx.x;
    } else {
        src = W; hi = g_w_hi; lo = g_w_lo;
        i = (bid - XBLOCKS) * 256 + threadIdx.x;
    }
    float4 v = reinterpret_cast<const float4*>(src)[i];
    float vv[4] = {v.x, v.y, v.z, v.w};
    unsigned short h[4], l[4];
#pragma unroll
    for (int j = 0; j < 4; j++) {
        __nv_bfloat16 hb = __float2bfloat16(vv[j]);
        __nv_bfloat16 lb = __float2bfloat16(vv[j] - __bfloat162float(hb));
        h[j] = __bfloat16_as_ushort(hb);
        l[j] = __bfloat16_as_ushort(lb);
    }
    reinterpret_cast<ushort4*>(hi)[i] = make_ushort4(h[0], h[1], h[2], h[3]);
    reinterpret_cast<ushort4*>(lo)[i] = make_ushort4(l[0], l[1], l[2], l[3]);
}

// ---------------- mma.sync GEMM + bias + tanh ----------------
// CTA tile 128x128, K-stage 64 bf16, 3 fused terms -> 48 stage-iterations.
// 8 warps in 2(M) x 4(N) grid; warp tile 64x32 via m16n8k16.
// 3 cp.async stages (96 KB) so TWO CTAs co-reside per SM (4 warps/SMSP).
static constexpr int NSTAGES  = 3;
static constexpr int A_BYTES  = 128 * 128;          // 128 rows x 64 bf16 (128B/row)
static constexpr int STAGE_B  = 2 * A_BYTES;        // A + B = 32 KB
static constexpr int SMEM_GB  = NSTAGES * STAGE_B;  // 96 KB
static constexpr int ITERS    = 3 * (DIM / 64);     // 48

__global__ __launch_bounds__(256, 2)
void gemm_kernel(const float* __restrict__ bias, float* __restrict__ out) {
    extern __shared__ char smem[];
    const uint32_t sb = smem_u32(smem);
    const int tid  = threadIdx.x;
    const int lane = tid & 31;
    const int wid  = tid >> 5;
    const int wm   = wid >> 2;       // 0..1 -> 64 rows
    const int wn   = wid & 3;        // 0..3 -> 32 cols
    const int m_base = blockIdx.y * 128;
    const int n_base = blockIdx.x * 128;

    // cp.async addressing: thread t -> row r = t>>1 (0..127), half h = t&1, 4x16B units
    const int r_ld = tid >> 1;
    const int h_ld = tid & 1;

    const __nv_bfloat16* xs[3] = {g_x_hi, g_x_hi, g_x_lo};
    const __nv_bfloat16* ws[3] = {g_w_hi, g_w_lo, g_w_hi};

    auto load_stage = [&](int it) {
        const int term = it >> 4;
        const int kc   = (it & 15) * 64;
        const int st   = (it % NSTAGES) * STAGE_B;
        const __nv_bfloat16* ga = xs[term] + (size_t)(m_base + r_ld) * DIM + kc;
        const __nv_bfloat16* gb = ws[term] + (size_t)(n_base + r_ld) * DIM + kc;
        const uint32_t sa  = sb + st + r_ld * 128;
        const uint32_t sbb = sb + st + A_BYTES + r_ld * 128;
        const int swz = r_ld & 7;
#pragma unroll
        for (int j = 0; j < 4; j++) {
            const int u = h_ld * 4 + j;
            const uint32_t so = (uint32_t)((u ^ swz) << 4);
            cp_async16(sa + so, ga + u * 8);
            cp_async16(sbb + so, gb + u * 8);
        }
    };

    float acc[4][4][4];
#pragma unroll
    for (int i = 0; i < 4; i++)
#pragma unroll
        for (int j = 0; j < 4; j++)
#pragma unroll
            for (int k = 0; k < 4; k++) acc[i][j][k] = 0.0f;

    // prologue: stages 0..1 in flight
    load_stage(0); cp_commit();
    load_stage(1); cp_commit();

    // per-lane ldmatrix row constants
    const int rA  = lane & 15;        // A: row within m16 tile
    const int uhA = lane >> 4;        // A: k 16B-unit half
    const int rB  = lane;             // B: row within warp's 32 n-rows (4 n-tiles)
    const int rowAc[4] = {wm * 64 + 0 * 16 + rA, wm * 64 + 1 * 16 + rA,
                          wm * 64 + 2 * 16 + rA, wm * 64 + 3 * 16 + rA};
    const int rowBc = wn * 32 + rB;

    // double-buffered fragments
    uint32_t a_f[2][4][4];
    uint32_t b_f[2][4][2];

    for (int it = 0; it < ITERS; it++) {
        if (it <= ITERS - 2) cp_wait<1>();
        else                 cp_wait<0>();
        __syncthreads();
        // Top barrier proves every warp finished reading stage (it+2)%3 in iter
        // it-1, so issuing its overwrite now is safe; no trailing barrier needed.
        if (it + 2 < ITERS) { load_stage(it + 2); cp_commit(); }

        const uint32_t aBase = sb + (it % NSTAGES) * STAGE_B;
        const uint32_t bBase = aBase + A_BYTES;

        // preload ks=0 fragments into buffer 0
#pragma unroll
        for (int i = 0; i < 4; i++) {
            const uint32_t u = (uint32_t)(uhA ^ (rowAc[i] & 7));
            ldsm_x4(a_f[0][i], aBase + rowAc[i] * 128 + (u << 4));
        }
#pragma unroll
        for (int uh = 0; uh < 2; uh++) {
            const uint32_t u = (uint32_t)(uh ^ (rowBc & 7));
            uint32_t t[4];
            ldsm_x4(t, bBase + rowBc * 128 + (u << 4));
            b_f[0][0][uh] = t[0]; b_f[0][1][uh] = t[1];
            b_f[0][2][uh] = t[2]; b_f[0][3][uh] = t[3];
        }

#pragma unroll
        for (int ks = 0; ks < 4; ks++) {
            const int cur = ks & 1, nxt = cur ^ 1;
            if (ks < 3) {
                // prefetch ks+1 fragments while HMMAs of ks issue
#pragma unroll
                for (int i = 0; i < 4; i++) {
                    const uint32_t u = (uint32_t)(((ks + 1) * 2 + uhA) ^ (rowAc[i] & 7));
                    ldsm_x4(a_f[nxt][i], aBase + rowAc[i] * 128 + (u << 4));
                }
#pragma unroll
                for (int uh = 0; uh < 2; uh++) {
                    const uint32_t u = (uint32_t)(((ks + 1) * 2 + uh) ^ (rowBc & 7));
                    uint32_t t[4];
                    ldsm_x4(t, bBase + rowBc * 128 + (u << 4));
                    b_f[nxt][0][uh] = t[0]; b_f[nxt][1][uh] = t[1];
                    b_f[nxt][2][uh] = t[2]; b_f[nxt][3][uh] = t[3];
                }
            }
#pragma unroll
            for (int i = 0; i < 4; i++)
#pragma unroll
                for (int j = 0; j < 4; j++) mma_bf16(acc[i][j], a_f[cur][i], b_f[cur][j]);
        }
    }

    // epilogue: bias + tanh + float2 stores
#pragma unroll
    for (int j = 0; j < 4; j++) {
        const int col0 = n_base + wn * 32 + j * 8 + (lane & 3) * 2;
        const float2 bv = *reinterpret_cast<const float2*>(bias + col0);
#pragma unroll
        for (int i = 0; i < 4; i++) {
            const int row0 = m_base + wm * 64 + i * 16 + (lane >> 2);
            float2 v0, v1;
            v0.x = tanhf(acc[i][j][0] + bv.x);
            v0.y = tanhf(acc[i][j][1] + bv.y);
            v1.x = tanhf(acc[i][j][2] + bv.x);
            v1.y = tanhf(acc[i][j][3] + bv.y);
            *reinterpret_cast<float2*>(out + (size_t)row0 * NOUT + col0) = v0;
            *reinterpret_cast<float2*>(out + (size_t)(row0 + 8) * NOUT + col0) = v1;
        }
    }
}

// ---------------- host launch ----------------
extern "C" void kernel_launch(void* const* d_in, const int* in_sizes, int n_in,
                              void* d_out, int out_size) {
    const float *x = nullptr, *W = nullptr, *b = nullptr;
    for (int i = 0; i < n_in; i++) {
        if (in_sizes[i] == SEQ * DIM)       x = (const float*)d_in[i];
        else if (in_sizes[i] == NOUT * DIM) W = (const float*)d_in[i];
        else if (in_sizes[i] == NOUT)       b = (const float*)d_in[i];
    }
    float* out = (float*)d_out;

    split_all_kernel<<<XBLOCKS + WBLOCKS, 256>>>(x, W);

    static bool attr_set = false;
    if (!attr_set) {
        cudaFuncSetAttribute(gemm_kernel, cudaFuncAttributeMaxDynamicSharedMemorySize, SMEM_GB);
        attr_set = true;
    }
    dim3 grid(NOUT / 128, SEQ / 128);  // (32, 64)
    gemm_kernel<<<grid, 256, SMEM_GB>>>(b, out);
}